// round 13
// baseline (speedup 1.0000x reference)
#include <cuda_runtime.h>
#include <cuda_fp16.h>

#define BB 4
#define SS 2048
#define EE 1024
#define HH 16
#define HD 64
#define NW 8
#define CHK 128          // keys per SMEM chunk in k_attn
#define KS32 12          // f32 words per key in kf32 tile (conflict-free)
#define KS16 136         // halves per dim row in kf16T tile (conflict-free)
#define ZK 128           // K dim of output GEMM
#define OS 136           // smem half-stride for k_out tiles (conflict-free)

typedef unsigned long long ull;
typedef unsigned int u32;
typedef unsigned short u16;

__device__ __forceinline__ u32 tf32r(float f){
    u32 u; asm("cvt.rna.tf32.f32 %0, %1;" : "=r"(u) : "f"(f)); return u;
}
__device__ __forceinline__ u32 f16x2of(float hi, float lo){
    u32 u; asm("cvt.rn.f16x2.f32 %0, %1, %2;" : "=r"(u) : "f"(hi), "f"(lo)); return u;
}
__device__ __forceinline__ u32 ex2h2(u32 s){
    u32 d; asm("ex2.approx.f16x2 %0, %1;" : "=r"(d) : "r"(s)); return d;
}
__device__ __forceinline__ u32 bf16x2of(float hi, float lo){
    u32 d; asm("cvt.rn.bf16x2.f32 %0, %1, %2;" : "=r"(d) : "f"(hi), "f"(lo)); return d;
}
__device__ __forceinline__ float bflo(u32 p){ return __uint_as_float(p << 16); }
__device__ __forceinline__ float bfhi(u32 p){ return __uint_as_float(p & 0xffff0000u); }
__device__ __forceinline__ void cpa16(void* s, const void* g){
    asm volatile("cp.async.ca.shared.global [%0], [%1], 16;"
        :: "r"((u32)__cvta_generic_to_shared(s)), "l"(g));
}
__device__ __forceinline__ void cpa_commit(){ asm volatile("cp.async.commit_group;"); }
template<int N> __device__ __forceinline__ void cpa_wait(){
    asm volatile("cp.async.wait_group %0;" :: "n"(N));
}
__device__ __forceinline__ void mma_tf32(float&c0,float&c1,float&c2,float&c3,
    u32 a0,u32 a1,u32 a2,u32 a3, u32 b0,u32 b1){
    asm("mma.sync.aligned.m16n8k8.row.col.f32.tf32.tf32.f32 "
        "{%0,%1,%2,%3}, {%4,%5,%6,%7}, {%8,%9}, {%10,%11,%12,%13};"
        : "=f"(c0),"=f"(c1),"=f"(c2),"=f"(c3)
        : "r"(a0),"r"(a1),"r"(a2),"r"(a3), "r"(b0),"r"(b1),
          "f"(0.f),"f"(0.f),"f"(0.f),"f"(0.f));
}
__device__ __forceinline__ void mma_f16(float&c0,float&c1,float&c2,float&c3,
    u32 a0,u32 a1,u32 a2,u32 a3, u32 b0,u32 b1){
    asm("mma.sync.aligned.m16n8k16.row.col.f32.f16.f16.f32 "
        "{%0,%1,%2,%3}, {%4,%5,%6,%7}, {%8,%9}, {%0,%1,%2,%3};"
        : "+f"(c0),"+f"(c1),"+f"(c2),"+f"(c3)
        : "r"(a0),"r"(a1),"r"(a2),"r"(a3), "r"(b0),"r"(b1));
}
__device__ __forceinline__ void mma_bf16(float&c0,float&c1,float&c2,float&c3,
    u32 a0,u32 a1,u32 a2,u32 a3, u32 b0,u32 b1){
    asm("mma.sync.aligned.m16n8k16.row.col.f32.bf16.bf16.f32 "
        "{%0,%1,%2,%3}, {%4,%5,%6,%7}, {%8,%9}, {%0,%1,%2,%3};"
        : "+f"(c0),"+f"(c1),"+f"(c2),"+f"(c3)
        : "r"(a0),"r"(a1),"r"(a2),"r"(a3), "r"(b0),"r"(b1));
}

// Scratch (static device memory — no allocations)
__device__ __align__(16) float g_qo[BB*SS*NW];        // cos(x+theta), tf32-pre-rounded f32
__device__ __align__(16) u16   g_kh[BB*NW*SS];        // keys fp16, [b][dim][key]
__device__ __align__(16) float g_qp[EE*NW];
__device__ __align__(16) float g_kp[EE*NW];
__device__ __align__(16) float g_vp[EE*NW];
__device__ __align__(16) float g_vpT[NW*EE];          // vp transposed: [i][e]
__device__ __align__(16) float g_M[HH*81];            // per-head 9x9 (log2e/8 folded)
__device__ __align__(16) float g_bias2[EE];           // out_w@v_b + out_b
__device__ __align__(16) u32   g_Zhi[BB*SS*ZK/2];     // z bf16 hi, [row][k] packed pairs
__device__ __align__(16) u32   g_Zlo[BB*SS*ZK/2];     // z bf16 lo
__device__ __align__(16) u16   g_GThi[EE*ZK];         // G^T bf16 hi, [e][k]
__device__ __align__(16) u16   g_GTlo[EE*ZK];         // G^T bf16 lo

// ---------------- K1: qo = tf32(cos(x[..., :8]+theta)); keys fp16 transposed ----------------
__global__ void k_qo(const float* __restrict__ x, const float* __restrict__ theta){
    int idx = blockIdx.x*blockDim.x + threadIdx.x;
    if (idx >= BB*SS*NW) return;
    int i = idx & 7;
    int row = idx >> 3;
    float v = cosf(x[(size_t)row*EE + i] + theta[i]);
    g_qo[idx] = __uint_as_float(tf32r(v));
    int b = row >> 11, key = row & 2047;
    __half hv = __float2half(v);
    g_kh[((size_t)b*NW + i)*SS + key] = *(u16*)&hv;
}

// ---------------- K2: qp/kp/vp[e][i] = sum_k W[e][k] * proj[k][i]; also vpT ----------------
__global__ void k_proj(const float* __restrict__ qw, const float* __restrict__ kw,
                       const float* __restrict__ vw, const float* __restrict__ proj){
    int gw = (blockIdx.x*blockDim.x + threadIdx.x) >> 5;
    int lane = threadIdx.x & 31;
    if (gw >= 3*EE) return;
    int mat = gw >> 10;
    int e = gw & 1023;
    const float* W = (mat==0) ? qw : (mat==1 ? kw : vw);
    float acc[8];
    #pragma unroll
    for (int i=0;i<8;i++) acc[i]=0.f;
    for (int k=lane; k<EE; k+=32){
        float wv = W[(size_t)e*EE + k];
        float4 p0 = *(const float4*)(proj + k*8);
        float4 p1 = *(const float4*)(proj + k*8 + 4);
        acc[0] += wv*p0.x; acc[1] += wv*p0.y; acc[2] += wv*p0.z; acc[3] += wv*p0.w;
        acc[4] += wv*p1.x; acc[5] += wv*p1.y; acc[6] += wv*p1.z; acc[7] += wv*p1.w;
    }
    #pragma unroll
    for (int off=16; off; off>>=1){
        #pragma unroll
        for (int i=0;i<8;i++) acc[i] += __shfl_down_sync(0xffffffffu, acc[i], off);
    }
    if (lane==0){
        float* dst = (mat==0 ? g_qp : (mat==1 ? g_kp : g_vp)) + e*8;
        *(float4*)dst     = make_float4(acc[0],acc[1],acc[2],acc[3]);
        *(float4*)(dst+4) = make_float4(acc[4],acc[5],acc[6],acc[7]);
        if (mat==2){
            #pragma unroll
            for (int i=0;i<8;i++) g_vpT[i*EE + e] = acc[i];
        }
    }
}

// ---------------- K3: per-head augmented 9x9 score matrix (log2e/8 folded) ----------------
__global__ void k_M(const float* __restrict__ qb, const float* __restrict__ kb){
    int h = blockIdx.x;
    int t = threadIdx.x;
    if (t >= 81) return;
    int i = t/9, j = t%9;
    float s = 0.f;
    #pragma unroll 8
    for (int d=0; d<HD; d++){
        int r = h*HD + d;
        float a  = (i<8) ? g_qp[r*8+i] : qb[r];
        float bv = (j<8) ? g_kp[r*8+j] : kb[r];
        s += a*bv;
    }
    g_M[h*81+t] = s * 0.125f * 1.4426950408889634f;
}

// ---------------- K4 v4: register-direct, 1 e-row per CTA, 1024 CTAs ----------------
// GT[e][j=h*8+i] = sum_d ow[e][h*64+d]*vpT[i][h*64+d] (bf16 split); bias2.
__global__ __launch_bounds__(128) void k_G(const float* __restrict__ ow, const float* __restrict__ vb,
                    const float* __restrict__ ob){
    __shared__ float pr[4];
    int e = blockIdx.x, tid = threadIdx.x;
    int h = tid >> 3, i = tid & 7;
    const float4* asrc = (const float4*)(ow + (size_t)e*EE + h*HD);
    const float4* vsrc = (const float4*)(g_vpT + (size_t)i*EE + h*HD);
    const float4* bsrc = (const float4*)(vb + h*HD);
    float s = 0.f, bacc = 0.f;
    #pragma unroll
    for (int q=0; q<16; q++){
        float4 a = asrc[q];
        float4 v = vsrc[q];
        s = fmaf(a.x,v.x, fmaf(a.y,v.y, fmaf(a.z,v.z, fmaf(a.w,v.w, s))));
        if (i==0){
            float4 bv = bsrc[q];
            bacc = fmaf(a.x,bv.x, fmaf(a.y,bv.y, fmaf(a.z,bv.z, fmaf(a.w,bv.w, bacc))));
        }
    }
    // bf16 hi/lo split write
    u32 p = bf16x2of(0.f, s);
    float shi = bflo(p);
    u32 pl = bf16x2of(0.f, s - shi);
    g_GThi[(size_t)e*ZK + tid] = (u16)(p & 0xffffu);
    g_GTlo[(size_t)e*ZK + tid] = (u16)(pl & 0xffffu);

    // bias2: only i==0 lanes carry a segment (h = w*4 + {0..3} at lanes 0,8,16,24)
    #pragma unroll
    for (int off=16; off; off>>=1) bacc += __shfl_down_sync(0xffffffffu, bacc, off);
    if ((tid & 31)==0) pr[tid>>5] = bacc;
    __syncthreads();
    if (tid==0) g_bias2[e] = pr[0]+pr[1]+pr[2]+pr[3] + ob[e];
}

// ---------------- K5: tensor-core attention, 4-buffer cp.async, 1 sync/chunk ----------------
__global__ __launch_bounds__(256) void k_attn(){
    __shared__ __align__(16) float sM[81];
    __shared__ __align__(16) float kf32[4][CHK*KS32];   // [key][dim] tf32 values, stride 12
    __shared__ __align__(16) __half kf16[4][8*KS16];    // [dim][key] fp16, stride 136
    int tid = threadIdx.x;
    int lane = tid & 31, w = tid >> 5;
    int b = blockIdx.z, h = blockIdx.y;
    int qbase = blockIdx.x*128 + w*16;
    int g = lane >> 2, c = lane & 3;

    if (tid < 81) sM[tid] = g_M[h*81 + tid];

    const float4* ksrc = (const float4*)(g_qo + (size_t)b*SS*NW);
    const uint4* hsrc = (const uint4*)(g_kh + (size_t)b*NW*SS);

    #define ISSUE(ch, bf) do{ \
        cpa16(&kf32[bf][(tid>>1)*KS32 + (tid&1)*4], ksrc + (ch)*256 + tid); \
        if (tid < 128){ int dim = tid>>4, seg = tid&15; \
            cpa16(&kf16[bf][dim*KS16 + seg*8], hsrc + (dim*SS + (ch)*CHK)/8 + seg); } \
        cpa_commit(); }while(0)

    ISSUE(0, 0);
    ISSUE(1, 1);
    ISSUE(2, 2);
    __syncthreads();   // sM ready (also first-buffer ordering vs compute below)

    // A fragment: t[row][col] for rows {g, g+8}, cols {c, c+4} (t8 constant dropped)
    const float* qA = g_qo + (size_t)(b*SS + qbase + g)*NW;
    const float* qB = qA + 8*NW;
    float qvA[8], qvB[8];
    #pragma unroll
    for (int i=0;i<8;i++){ qvA[i]=qA[i]; qvB[i]=qB[i]; }
    float tA0 = sM[72+c],   tB0 = sM[72+c];
    float tA1 = sM[72+c+4], tB1 = sM[72+c+4];
    #pragma unroll
    for (int i=0;i<8;i++){
        tA0 += qvA[i]*sM[i*9+c];   tB0 += qvB[i]*sM[i*9+c];
        tA1 += qvA[i]*sM[i*9+c+4]; tB1 += qvB[i]*sM[i*9+c+4];
    }
    u32 a0 = tf32r(tA0), a1 = tf32r(tB0), a2 = tf32r(tA1), a3 = tf32r(tB1);

    float zc0=0.f, zc1=0.f, zc2=0.f, zc3=0.f;
    float lc0=0.f, lc1=0.f, lc2=0.f, lc3=0.f;
    u32 bone = (g==0) ? 0x3C003C00u : 0u;

    #pragma unroll 1
    for (int ch=0; ch<SS/CHK; ch++){
        // group ch must be complete: pending allowed = min(16,ch+3)-(ch+1)
        if (ch <= 13)      cpa_wait<2>();
        else if (ch == 14) cpa_wait<1>();
        else               cpa_wait<0>();
        __syncthreads();
        // issue ch+3 into buffer (ch+3)&3 == (ch-1)&3, freed by the sync above
        if (ch + 3 < SS/CHK) ISSUE(ch+3, (ch+3)&3);
        int bf = ch & 3;
        const float*  kw32 = kf32[bf];
        const __half* kw16 = kf16[bf];
        #pragma unroll
        for (int t16=0; t16<CHK/16; t16++){
            int k0 = t16*16;
            u32 b0 = __float_as_uint(kw32[(k0+g)*KS32 + c]);
            u32 b1 = __float_as_uint(kw32[(k0+g)*KS32 + c + 4]);
            u32 b2 = __float_as_uint(kw32[(k0+8+g)*KS32 + c]);
            u32 b3 = __float_as_uint(kw32[(k0+8+g)*KS32 + c + 4]);
            float c0,c1,c2,c3, d0,d1,d2,d3;
            mma_tf32(c0,c1,c2,c3, a0,a1,a2,a3, b0,b1);
            mma_tf32(d0,d1,d2,d3, a0,a1,a2,a3, b2,b3);
            u32 p0 = ex2h2(f16x2of(c1, c0));
            u32 p1 = ex2h2(f16x2of(c3, c2));
            u32 p2 = ex2h2(f16x2of(d1, d0));
            u32 p3 = ex2h2(f16x2of(d3, d2));
            u32 vb0 = *(const u32*)&kw16[g*KS16 + k0 + c*2];
            u32 vb1 = *(const u32*)&kw16[g*KS16 + k0 + c*2 + 8];
            mma_f16(zc0,zc1,zc2,zc3, p0,p1,p2,p3, vb0,vb1);
            mma_f16(lc0,lc1,lc2,lc3, p0,p1,p2,p3, bone,bone);
        }
    }
    #undef ISSUE

    float la = __shfl_sync(0xffffffffu, lc0, lane & ~3);
    float lb = __shfl_sync(0xffffffffu, lc2, lane & ~3);
    float ia = 1.0f/la, ib = 1.0f/lb;
    float z0 = zc0*ia, z1 = zc1*ia, z2 = zc2*ib, z3 = zc3*ib;

    // bf16 hi/lo split writes: g_Z*[row][k] with k = h*8 + c*2 (.x), +1 (.y)
    int rowA = b*SS + qbase + g;
    size_t iA = (size_t)rowA*(ZK/2) + h*4 + c;
    size_t iB = iA + 8*(ZK/2);
    u32 hA = bf16x2of(z1, z0);
    u32 lA = bf16x2of(z1 - bfhi(hA), z0 - bflo(hA));
    u32 hB = bf16x2of(z3, z2);
    u32 lB = bf16x2of(z3 - bfhi(hB), z2 - bflo(hB));
    g_Zhi[iA] = hA; g_Zlo[iA] = lA;
    g_Zhi[iB] = hB; g_Zlo[iB] = lB;
}

// ---------------- K6: out = Z @ G^T + bias2, bf16-split tensor-core GEMM ----------------
__global__ __launch_bounds__(256) void k_out(float* __restrict__ out){
    extern __shared__ __align__(16) char smem[];
    __half* sZh = (__half*)smem;                 // [128][OS]
    __half* sZl = sZh + 128*OS;
    __half* sGh = sZl + 128*OS;                  // [e 128][OS]
    __half* sGl = sGh + 128*OS;
    float*  sB  = (float*)(sGl + 128*OS);        // 128 bias values

    int tid = threadIdx.x;
    int lane = tid & 31, w = tid >> 5;
    int g = lane >> 2, c = lane & 3;
    int rbase = blockIdx.x*128;
    int ebase = blockIdx.y*128;

    const uint4* zh4 = (const uint4*)g_Zhi;
    const uint4* zl4 = (const uint4*)g_Zlo;
    const uint4* gh4 = (const uint4*)g_GThi;
    const uint4* gl4 = (const uint4*)g_GTlo;
    #pragma unroll
    for (int q=tid; q<2048; q+=256){
        int r = q >> 4, seg = q & 15;
        *(uint4*)&sZh[r*OS + seg*8] = zh4[((size_t)(rbase+r)*ZK)/8 + seg];
        *(uint4*)&sZl[r*OS + seg*8] = zl4[((size_t)(rbase+r)*ZK)/8 + seg];
        *(uint4*)&sGh[r*OS + seg*8] = gh4[((size_t)(ebase+r)*ZK)/8 + seg];
        *(uint4*)&sGl[r*OS + seg*8] = gl4[((size_t)(ebase+r)*ZK)/8 + seg];
    }
    if (tid < 128) sB[tid] = g_bias2[ebase + tid];
    __syncthreads();

    float acc[16][4];
    #pragma unroll
    for (int nt=0;nt<16;nt++){ acc[nt][0]=0.f; acc[nt][1]=0.f; acc[nt][2]=0.f; acc[nt][3]=0.f; }

    int rA = w*16 + g;
    #pragma unroll
    for (int ks=0; ks<8; ks++){
        int kb = ks*16 + c*2;
        u32 ah0 = *(const u32*)&sZh[rA*OS + kb];
        u32 ah1 = *(const u32*)&sZh[(rA+8)*OS + kb];
        u32 ah2 = *(const u32*)&sZh[rA*OS + kb + 8];
        u32 ah3 = *(const u32*)&sZh[(rA+8)*OS + kb + 8];
        u32 al0 = *(const u32*)&sZl[rA*OS + kb];
        u32 al1 = *(const u32*)&sZl[(rA+8)*OS + kb];
        u32 al2 = *(const u32*)&sZl[rA*OS + kb + 8];
        u32 al3 = *(const u32*)&sZl[(rA+8)*OS + kb + 8];
        #pragma unroll
        for (int nt=0; nt<16; nt++){
            int eg = nt*8 + g;
            u32 bh0 = *(const u32*)&sGh[eg*OS + kb];
            u32 bh1 = *(const u32*)&sGh[eg*OS + kb + 8];
            u32 bl0 = *(const u32*)&sGl[eg*OS + kb];
            u32 bl1 = *(const u32*)&sGl[eg*OS + kb + 8];
            mma_bf16(acc[nt][0],acc[nt][1],acc[nt][2],acc[nt][3], ah0,ah1,ah2,ah3, bh0,bh1);
            mma_bf16(acc[nt][0],acc[nt][1],acc[nt][2],acc[nt][3], ah0,ah1,ah2,ah3, bl0,bl1);
            mma_bf16(acc[nt][0],acc[nt][1],acc[nt][2],acc[nt][3], al0,al1,al2,al3, bh0,bh1);
        }
    }

    int row0 = rbase + w*16 + g;
    #pragma unroll
    for (int nt=0; nt<16; nt++){
        int col = nt*8 + c*2;
        float b0v = sB[col], b1v = sB[col+1];
        float* o0 = out + (size_t)row0*EE + ebase + col;
        *(float2*)o0 = make_float2(acc[nt][0]+b0v, acc[nt][1]+b1v);
        float* o1 = o0 + (size_t)8*EE;
        *(float2*)o1 = make_float2(acc[nt][2]+b0v, acc[nt][3]+b1v);
    }
}

extern "C" void kernel_launch(void* const* d_in, const int* in_sizes, int n_in,
                              void* d_out, int out_size){
    (void)in_sizes; (void)n_in; (void)out_size;
    const float* x     = (const float*)d_in[0];
    const float* theta = (const float*)d_in[1];
    const float* proj  = (const float*)d_in[2];
    const float* qw    = (const float*)d_in[3];
    const float* qb    = (const float*)d_in[4];
    const float* kw    = (const float*)d_in[5];
    const float* kb    = (const float*)d_in[6];
    const float* vw    = (const float*)d_in[7];
    const float* vb    = (const float*)d_in[8];
    const float* ow    = (const float*)d_in[9];
    const float* ob    = (const float*)d_in[10];
    float* out = (float*)d_out;

    const int OUT_SMEM = 4*128*OS*2 + 128*4;   // 139,776 B
    cudaFuncSetAttribute(k_out, cudaFuncAttributeMaxDynamicSharedMemorySize, OUT_SMEM);

    k_qo  <<<(BB*SS*NW + 255)/256, 256>>>(x, theta);
    k_proj<<<(3*EE*32 + 255)/256, 256>>>(qw, kw, vw, proj);
    k_M   <<<HH, 96>>>(qb, kb);
    k_G   <<<EE, 128>>>(ow, vb, ob);
    k_attn<<<dim3(SS/128, HH, BB), 256>>>();
    k_out <<<dim3(BB*SS/128, EE/128), 256, OUT_SMEM>>>(out);
}

// round 17
// speedup vs baseline: 1.0897x; 1.0897x over previous
#include <cuda_runtime.h>
#include <cuda_fp16.h>

#define BB 4
#define SS 2048
#define EE 1024
#define HH 16
#define HD 64
#define NW 8
#define CHK 128          // keys per SMEM chunk in k_attn
#define KS32 12          // f32 words per key in kf32 tile (conflict-free)
#define KS16 136         // halves per dim row in kf16T tile (conflict-free)
#define ZK 128           // K dim of output GEMM
#define OS 136           // smem half-stride for k_out tiles (conflict-free)
#define GROW 1088        // skewed row stride (words) in k_G: [h*68+d]

typedef unsigned long long ull;
typedef unsigned int u32;
typedef unsigned short u16;

__device__ __forceinline__ u32 tf32r(float f){
    u32 u; asm("cvt.rna.tf32.f32 %0, %1;" : "=r"(u) : "f"(f)); return u;
}
__device__ __forceinline__ u32 f16x2of(float hi, float lo){
    u32 u; asm("cvt.rn.f16x2.f32 %0, %1, %2;" : "=r"(u) : "f"(hi), "f"(lo)); return u;
}
__device__ __forceinline__ u32 ex2h2(u32 s){
    u32 d; asm("ex2.approx.f16x2 %0, %1;" : "=r"(d) : "r"(s)); return d;
}
__device__ __forceinline__ u32 bf16x2of(float hi, float lo){
    u32 d; asm("cvt.rn.bf16x2.f32 %0, %1, %2;" : "=r"(d) : "f"(hi), "f"(lo)); return d;
}
__device__ __forceinline__ float bflo(u32 p){ return __uint_as_float(p << 16); }
__device__ __forceinline__ float bfhi(u32 p){ return __uint_as_float(p & 0xffff0000u); }
__device__ __forceinline__ void cpa16(void* s, const void* g){
    asm volatile("cp.async.ca.shared.global [%0], [%1], 16;"
        :: "r"((u32)__cvta_generic_to_shared(s)), "l"(g));
}
__device__ __forceinline__ void cpa_commit(){ asm volatile("cp.async.commit_group;"); }
template<int N> __device__ __forceinline__ void cpa_wait(){
    asm volatile("cp.async.wait_group %0;" :: "n"(N));
}
__device__ __forceinline__ void mma_tf32(float&c0,float&c1,float&c2,float&c3,
    u32 a0,u32 a1,u32 a2,u32 a3, u32 b0,u32 b1){
    asm("mma.sync.aligned.m16n8k8.row.col.f32.tf32.tf32.f32 "
        "{%0,%1,%2,%3}, {%4,%5,%6,%7}, {%8,%9}, {%10,%11,%12,%13};"
        : "=f"(c0),"=f"(c1),"=f"(c2),"=f"(c3)
        : "r"(a0),"r"(a1),"r"(a2),"r"(a3), "r"(b0),"r"(b1),
          "f"(0.f),"f"(0.f),"f"(0.f),"f"(0.f));
}
__device__ __forceinline__ void mma_f16(float&c0,float&c1,float&c2,float&c3,
    u32 a0,u32 a1,u32 a2,u32 a3, u32 b0,u32 b1){
    asm("mma.sync.aligned.m16n8k16.row.col.f32.f16.f16.f32 "
        "{%0,%1,%2,%3}, {%4,%5,%6,%7}, {%8,%9}, {%0,%1,%2,%3};"
        : "+f"(c0),"+f"(c1),"+f"(c2),"+f"(c3)
        : "r"(a0),"r"(a1),"r"(a2),"r"(a3), "r"(b0),"r"(b1));
}
__device__ __forceinline__ void mma_bf16(float&c0,float&c1,float&c2,float&c3,
    u32 a0,u32 a1,u32 a2,u32 a3, u32 b0,u32 b1){
    asm("mma.sync.aligned.m16n8k16.row.col.f32.bf16.bf16.f32 "
        "{%0,%1,%2,%3}, {%4,%5,%6,%7}, {%8,%9}, {%0,%1,%2,%3};"
        : "+f"(c0),"+f"(c1),"+f"(c2),"+f"(c3)
        : "r"(a0),"r"(a1),"r"(a2),"r"(a3), "r"(b0),"r"(b1));
}

// Scratch (static device memory — no allocations)
__device__ __align__(16) float g_qo[BB*SS*NW];        // cos(x+theta), tf32-pre-rounded f32
__device__ __align__(16) u16   g_kh[BB*NW*SS];        // keys fp16, [b][dim][key]
__device__ __align__(16) float g_qp[EE*NW];
__device__ __align__(16) float g_kp[EE*NW];
__device__ __align__(16) float g_vp[EE*NW];
__device__ __align__(16) float g_M[HH*81];            // per-head 9x9 (log2e/8 folded)
__device__ __align__(16) float g_bias2[EE];           // out_w@v_b + out_b
__device__ __align__(16) u32   g_Zhi[BB*SS*ZK/2];     // z bf16 hi, [row][k] packed pairs
__device__ __align__(16) u32   g_Zlo[BB*SS*ZK/2];     // z bf16 lo
__device__ __align__(16) u16   g_GThi[EE*ZK];         // G^T bf16 hi, [e][k]
__device__ __align__(16) u16   g_GTlo[EE*ZK];         // G^T bf16 lo

// ---------------- K1: qo = tf32(cos(x[..., :8]+theta)); keys fp16 transposed ----------------
__global__ void k_qo(const float* __restrict__ x, const float* __restrict__ theta){
    int idx = blockIdx.x*blockDim.x + threadIdx.x;
    if (idx >= BB*SS*NW) return;
    int i = idx & 7;
    int row = idx >> 3;
    float v = cosf(x[(size_t)row*EE + i] + theta[i]);
    g_qo[idx] = __uint_as_float(tf32r(v));
    int b = row >> 11, key = row & 2047;
    __half hv = __float2half(v);
    g_kh[((size_t)b*NW + i)*SS + key] = *(u16*)&hv;
}

// ---------------- K2: qp/kp/vp[e][i] = sum_k W[e][k] * proj[k][i] ----------------
__global__ void k_proj(const float* __restrict__ qw, const float* __restrict__ kw,
                       const float* __restrict__ vw, const float* __restrict__ proj){
    int gw = (blockIdx.x*blockDim.x + threadIdx.x) >> 5;
    int lane = threadIdx.x & 31;
    if (gw >= 3*EE) return;
    int mat = gw >> 10;
    int e = gw & 1023;
    const float* W = (mat==0) ? qw : (mat==1 ? kw : vw);
    float acc[8];
    #pragma unroll
    for (int i=0;i<8;i++) acc[i]=0.f;
    for (int k=lane; k<EE; k+=32){
        float wv = W[(size_t)e*EE + k];
        float4 p0 = *(const float4*)(proj + k*8);
        float4 p1 = *(const float4*)(proj + k*8 + 4);
        acc[0] += wv*p0.x; acc[1] += wv*p0.y; acc[2] += wv*p0.z; acc[3] += wv*p0.w;
        acc[4] += wv*p1.x; acc[5] += wv*p1.y; acc[6] += wv*p1.z; acc[7] += wv*p1.w;
    }
    #pragma unroll
    for (int off=16; off; off>>=1){
        #pragma unroll
        for (int i=0;i<8;i++) acc[i] += __shfl_down_sync(0xffffffffu, acc[i], off);
    }
    if (lane==0){
        float* dst = (mat==0 ? g_qp : (mat==1 ? g_kp : g_vp)) + e*8;
        *(float4*)dst     = make_float4(acc[0],acc[1],acc[2],acc[3]);
        *(float4*)(dst+4) = make_float4(acc[4],acc[5],acc[6],acc[7]);
    }
}

// ---------------- K3: per-head augmented 9x9 score matrix (log2e/8 folded) ----------------
__global__ void k_M(const float* __restrict__ qb, const float* __restrict__ kb){
    int h = blockIdx.x;
    int t = threadIdx.x;
    if (t >= 81) return;
    int i = t/9, j = t%9;
    float s = 0.f;
    #pragma unroll 8
    for (int d=0; d<HD; d++){
        int r = h*HD + d;
        float a  = (i<8) ? g_qp[r*8+i] : qb[r];
        float bv = (j<8) ? g_kp[r*8+j] : kb[r];
        s += a*bv;
    }
    g_M[h*81+t] = s * 0.125f * 1.4426950408889634f;
}

// ---------------- K4 (R11-proven): 4 e-rows per CTA, skewed smem ----------------
// GT[e][j=h*8+i] = sum_d ow[e][h*64+d]*vp[h*64+d][i] (bf16 split); bias2.
__global__ __launch_bounds__(256) void k_G(const float* __restrict__ ow, const float* __restrict__ vb,
                    const float* __restrict__ ob){
    __shared__ __align__(16) float rows[4*GROW];   // skewed: word = r*GROW + h*68 + d
    __shared__ float pr[16];
    int tid = threadIdx.x;
    int e0 = blockIdx.x*4;

    // cooperative load: 4 rows x 1024 f32 = 1024 float4, skew +4h words
    const float4* src = (const float4*)(ow + (size_t)e0*EE);
    #pragma unroll
    for (int q=tid; q<1024; q+=256){
        int r = q >> 8;
        int k = (q & 255)*4;
        int h = k >> 6;
        *(float4*)&rows[r*GROW + k + h*4] = src[q];
    }
    __syncthreads();

    // thread (sub = tid>>7, j = tid&127) computes rows {sub, sub+2}
    int sub = tid >> 7, j = tid & 127;
    int h = j >> 3, i = j & 7;
    const float* r0 = rows + sub*GROW + h*68;
    const float* r2 = r0 + 2*GROW;
    float s0 = 0.f, s1 = 0.f;
    #pragma unroll 8
    for (int d=0; d<HD; d++){
        float v = g_vp[(h*HD + d)*NW + i];
        s0 = fmaf(r0[d], v, s0);
        s1 = fmaf(r2[d], v, s1);
    }
    // bf16 hi/lo split writes
    u32 p0 = bf16x2of(0.f, s0); float h0v = bflo(p0); u32 q0 = bf16x2of(0.f, s0 - h0v);
    u32 p1 = bf16x2of(0.f, s1); float h1v = bflo(p1); u32 q1 = bf16x2of(0.f, s1 - h1v);
    g_GThi[(size_t)(e0+sub)*ZK + j]   = (u16)(p0 & 0xffffu);
    g_GTlo[(size_t)(e0+sub)*ZK + j]   = (u16)(q0 & 0xffffu);
    g_GThi[(size_t)(e0+sub+2)*ZK + j] = (u16)(p1 & 0xffffu);
    g_GTlo[(size_t)(e0+sub+2)*ZK + j] = (u16)(q1 & 0xffffu);

    // bias2 for the 4 rows: thread accumulates rows {sub, sub+2}
    float b0 = 0.f, b1 = 0.f;
    #pragma unroll 8
    for (int k=j; k<EE; k+=128){
        int sk = k + ((k >> 6) << 2);
        float vv = vb[k];
        b0 += rows[sub*GROW + sk]*vv;
        b1 += rows[(sub+2)*GROW + sk]*vv;
    }
    #pragma unroll
    for (int off=16; off; off>>=1){
        b0 += __shfl_down_sync(0xffffffffu, b0, off);
        b1 += __shfl_down_sync(0xffffffffu, b1, off);
    }
    if ((tid & 31)==0){
        int w = tid >> 5;
        pr[w*2]   = b0;
        pr[w*2+1] = b1;
    }
    __syncthreads();
    if (tid < 4){
        int base = (tid & 1)*8;
        int off  = (tid >> 1) & 1;
        float s = pr[base+off] + pr[base+off+2] + pr[base+off+4] + pr[base+off+6];
        g_bias2[e0 + tid] = s + ob[e0 + tid];
    }
}

// ---------------- K5: tensor-core attention, 4-buffer cp.async, 1 sync/chunk ----------------
__global__ __launch_bounds__(256) void k_attn(){
    __shared__ __align__(16) float sM[81];
    __shared__ __align__(16) float kf32[4][CHK*KS32];   // [key][dim] tf32 values, stride 12
    __shared__ __align__(16) __half kf16[4][8*KS16];    // [dim][key] fp16, stride 136
    int tid = threadIdx.x;
    int lane = tid & 31, w = tid >> 5;
    int b = blockIdx.z, h = blockIdx.y;
    int qbase = blockIdx.x*128 + w*16;
    int g = lane >> 2, c = lane & 3;

    if (tid < 81) sM[tid] = g_M[h*81 + tid];

    const float4* ksrc = (const float4*)(g_qo + (size_t)b*SS*NW);
    const uint4* hsrc = (const uint4*)(g_kh + (size_t)b*NW*SS);

    #define ISSUE(ch, bf) do{ \
        cpa16(&kf32[bf][(tid>>1)*KS32 + (tid&1)*4], ksrc + (ch)*256 + tid); \
        if (tid < 128){ int dim = tid>>4, seg = tid&15; \
            cpa16(&kf16[bf][dim*KS16 + seg*8], hsrc + (dim*SS + (ch)*CHK)/8 + seg); } \
        cpa_commit(); }while(0)

    ISSUE(0, 0);
    ISSUE(1, 1);
    ISSUE(2, 2);
    __syncthreads();   // sM ready (also first-buffer ordering vs compute below)

    // A fragment: t[row][col] for rows {g, g+8}, cols {c, c+4} (t8 constant dropped)
    const float* qA = g_qo + (size_t)(b*SS + qbase + g)*NW;
    const float* qB = qA + 8*NW;
    float qvA[8], qvB[8];
    #pragma unroll
    for (int i=0;i<8;i++){ qvA[i]=qA[i]; qvB[i]=qB[i]; }
    float tA0 = sM[72+c],   tB0 = sM[72+c];
    float tA1 = sM[72+c+4], tB1 = sM[72+c+4];
    #pragma unroll
    for (int i=0;i<8;i++){
        tA0 += qvA[i]*sM[i*9+c];   tB0 += qvB[i]*sM[i*9+c];
        tA1 += qvA[i]*sM[i*9+c+4]; tB1 += qvB[i]*sM[i*9+c+4];
    }
    u32 a0 = tf32r(tA0), a1 = tf32r(tB0), a2 = tf32r(tA1), a3 = tf32r(tB1);

    float zc0=0.f, zc1=0.f, zc2=0.f, zc3=0.f;
    float lc0=0.f, lc1=0.f, lc2=0.f, lc3=0.f;
    u32 bone = (g==0) ? 0x3C003C00u : 0u;

    #pragma unroll 1
    for (int ch=0; ch<SS/CHK; ch++){
        if (ch <= 13)      cpa_wait<2>();
        else if (ch == 14) cpa_wait<1>();
        else               cpa_wait<0>();
        __syncthreads();
        if (ch + 3 < SS/CHK) ISSUE(ch+3, (ch+3)&3);
        int bf = ch & 3;
        const float*  kw32 = kf32[bf];
        const __half* kw16 = kf16[bf];
        #pragma unroll
        for (int t16=0; t16<CHK/16; t16++){
            int k0 = t16*16;
            u32 b0 = __float_as_uint(kw32[(k0+g)*KS32 + c]);
            u32 b1 = __float_as_uint(kw32[(k0+g)*KS32 + c + 4]);
            u32 b2 = __float_as_uint(kw32[(k0+8+g)*KS32 + c]);
            u32 b3 = __float_as_uint(kw32[(k0+8+g)*KS32 + c + 4]);
            float c0,c1,c2,c3, d0,d1,d2,d3;
            mma_tf32(c0,c1,c2,c3, a0,a1,a2,a3, b0,b1);
            mma_tf32(d0,d1,d2,d3, a0,a1,a2,a3, b2,b3);
            u32 p0 = ex2h2(f16x2of(c1, c0));
            u32 p1 = ex2h2(f16x2of(c3, c2));
            u32 p2 = ex2h2(f16x2of(d1, d0));
            u32 p3 = ex2h2(f16x2of(d3, d2));
            u32 vb0 = *(const u32*)&kw16[g*KS16 + k0 + c*2];
            u32 vb1 = *(const u32*)&kw16[g*KS16 + k0 + c*2 + 8];
            mma_f16(zc0,zc1,zc2,zc3, p0,p1,p2,p3, vb0,vb1);
            mma_f16(lc0,lc1,lc2,lc3, p0,p1,p2,p3, bone,bone);
        }
    }
    #undef ISSUE

    float la = __shfl_sync(0xffffffffu, lc0, lane & ~3);
    float lb = __shfl_sync(0xffffffffu, lc2, lane & ~3);
    float ia = 1.0f/la, ib = 1.0f/lb;
    float z0 = zc0*ia, z1 = zc1*ia, z2 = zc2*ib, z3 = zc3*ib;

    // bf16 hi/lo split writes: g_Z*[row][k] with k = h*8 + c*2 (.x), +1 (.y)
    int rowA = b*SS + qbase + g;
    size_t iA = (size_t)rowA*(ZK/2) + h*4 + c;
    size_t iB = iA + 8*(ZK/2);
    u32 hA = bf16x2of(z1, z0);
    u32 lA = bf16x2of(z1 - bfhi(hA), z0 - bflo(hA));
    u32 hB = bf16x2of(z3, z2);
    u32 lB = bf16x2of(z3 - bfhi(hB), z2 - bflo(hB));
    g_Zhi[iA] = hA; g_Zlo[iA] = lA;
    g_Zhi[iB] = hB; g_Zlo[iB] = lB;
}

// ---------------- K6: out = Z @ G^T + bias2, bf16-split tensor-core GEMM ----------------
__global__ __launch_bounds__(256) void k_out(float* __restrict__ out){
    extern __shared__ __align__(16) char smem[];
    __half* sZh = (__half*)smem;                 // [128][OS]
    __half* sZl = sZh + 128*OS;
    __half* sGh = sZl + 128*OS;                  // [e 128][OS]
    __half* sGl = sGh + 128*OS;
    float*  sB  = (float*)(sGl + 128*OS);        // 128 bias values

    int tid = threadIdx.x;
    int lane = tid & 31, w = tid >> 5;
    int g = lane >> 2, c = lane & 3;
    int rbase = blockIdx.x*128;
    int ebase = blockIdx.y*128;

    const uint4* zh4 = (const uint4*)g_Zhi;
    const uint4* zl4 = (const uint4*)g_Zlo;
    const uint4* gh4 = (const uint4*)g_GThi;
    const uint4* gl4 = (const uint4*)g_GTlo;
    #pragma unroll
    for (int q=tid; q<2048; q+=256){
        int r = q >> 4, seg = q & 15;
        *(uint4*)&sZh[r*OS + seg*8] = zh4[((size_t)(rbase+r)*ZK)/8 + seg];
        *(uint4*)&sZl[r*OS + seg*8] = zl4[((size_t)(rbase+r)*ZK)/8 + seg];
        *(uint4*)&sGh[r*OS + seg*8] = gh4[((size_t)(ebase+r)*ZK)/8 + seg];
        *(uint4*)&sGl[r*OS + seg*8] = gl4[((size_t)(ebase+r)*ZK)/8 + seg];
    }
    if (tid < 128) sB[tid] = g_bias2[ebase + tid];
    __syncthreads();

    float acc[16][4];
    #pragma unroll
    for (int nt=0;nt<16;nt++){ acc[nt][0]=0.f; acc[nt][1]=0.f; acc[nt][2]=0.f; acc[nt][3]=0.f; }

    int rA = w*16 + g;
    #pragma unroll
    for (int ks=0; ks<8; ks++){
        int kb = ks*16 + c*2;
        u32 ah0 = *(const u32*)&sZh[rA*OS + kb];
        u32 ah1 = *(const u32*)&sZh[(rA+8)*OS + kb];
        u32 ah2 = *(const u32*)&sZh[rA*OS + kb + 8];
        u32 ah3 = *(const u32*)&sZh[(rA+8)*OS + kb + 8];
        u32 al0 = *(const u32*)&sZl[rA*OS + kb];
        u32 al1 = *(const u32*)&sZl[(rA+8)*OS + kb];
        u32 al2 = *(const u32*)&sZl[rA*OS + kb + 8];
        u32 al3 = *(const u32*)&sZl[(rA+8)*OS + kb + 8];
        #pragma unroll
        for (int nt=0; nt<16; nt++){
            int eg = nt*8 + g;
            u32 bh0 = *(const u32*)&sGh[eg*OS + kb];
            u32 bh1 = *(const u32*)&sGh[eg*OS + kb + 8];
            u32 bl0 = *(const u32*)&sGl[eg*OS + kb];
            u32 bl1 = *(const u32*)&sGl[eg*OS + kb + 8];
            mma_bf16(acc[nt][0],acc[nt][1],acc[nt][2],acc[nt][3], ah0,ah1,ah2,ah3, bh0,bh1);
            mma_bf16(acc[nt][0],acc[nt][1],acc[nt][2],acc[nt][3], ah0,ah1,ah2,ah3, bl0,bl1);
            mma_bf16(acc[nt][0],acc[nt][1],acc[nt][2],acc[nt][3], al0,al1,al2,al3, bh0,bh1);
        }
    }

    int row0 = rbase + w*16 + g;
    #pragma unroll
    for (int nt=0; nt<16; nt++){
        int col = nt*8 + c*2;
        float b0v = sB[col], b1v = sB[col+1];
        float* o0 = out + (size_t)row0*EE + ebase + col;
        *(float2*)o0 = make_float2(acc[nt][0]+b0v, acc[nt][1]+b1v);
        float* o1 = o0 + (size_t)8*EE;
        *(float2*)o1 = make_float2(acc[nt][2]+b0v, acc[nt][3]+b1v);
    }
}

extern "C" void kernel_launch(void* const* d_in, const int* in_sizes, int n_in,
                              void* d_out, int out_size){
    (void)in_sizes; (void)n_in; (void)out_size;
    const float* x     = (const float*)d_in[0];
    const float* theta = (const float*)d_in[1];
    const float* proj  = (const float*)d_in[2];
    const float* qw    = (const float*)d_in[3];
    const float* qb    = (const float*)d_in[4];
    const float* kw    = (const float*)d_in[5];
    const float* kb    = (const float*)d_in[6];
    const float* vw    = (const float*)d_in[7];
    const float* vb    = (const float*)d_in[8];
    const float* ow    = (const float*)d_in[9];
    const float* ob    = (const float*)d_in[10];
    float* out = (float*)d_out;

    const int OUT_SMEM = 4*128*OS*2 + 128*4;   // 139,776 B
    cudaFuncSetAttribute(k_out, cudaFuncAttributeMaxDynamicSharedMemorySize, OUT_SMEM);

    // One-time infra (streams/events are not device memory; captured work is
    // identical on every call).
    static cudaStream_t sB = nullptr;
    static cudaEvent_t evRoot = nullptr, evProj = nullptr, evG = nullptr;
    if (sB == nullptr){
        cudaStreamCreateWithFlags(&sB, cudaStreamNonBlocking);
        cudaEventCreateWithFlags(&evRoot, cudaEventDisableTiming);
        cudaEventCreateWithFlags(&evProj, cudaEventDisableTiming);
        cudaEventCreateWithFlags(&evG,    cudaEventDisableTiming);
    }

    // Fork: side branch (k_proj -> k_G) runs concurrently with the critical
    // path (k_qo -> k_M -> k_attn). k_M waits on k_proj; k_out joins on k_G.
    cudaEventRecord(evRoot, 0);
    cudaStreamWaitEvent(sB, evRoot, 0);

    k_proj<<<(3*EE*32 + 255)/256, 256, 0, sB>>>(qw, kw, vw, proj);
    cudaEventRecord(evProj, sB);
    k_G  <<<EE/4, 256, 0, sB>>>(ow, vb, ob);
    cudaEventRecord(evG, sB);

    k_qo  <<<(BB*SS*NW + 255)/256, 256>>>(x, theta);
    cudaStreamWaitEvent(0, evProj, 0);
    k_M   <<<HH, 96>>>(qb, kb);
    k_attn<<<dim3(SS/128, HH, BB), 256>>>();
    cudaStreamWaitEvent(0, evG, 0);
    k_out <<<dim3(BB*SS/128, EE/128), 256, OUT_SMEM>>>(out);
}